// round 8
// baseline (speedup 1.0000x reference)
#include <cuda_runtime.h>
#include <cstdint>

// NoReFT on [B,768] fp32, regions start {0,752,184,568}, width 16.
// Warp-specialized full-TMA pipeline:
//   loader warp:  bulk G->S into 6-stage x 12KB ring
//   256 fixup thr: in-smem patch of 64 edited ch/row (256 floats/tile)
//   storer warp:  bulk S->G, releases stages with wait_group.read slack
// No __syncthreads in the main loop.

#define T_ROWS 4
#define TILE_F (T_ROWS * 768)            // 3072 floats
#define TILE_BYTES (TILE_F * 4)          // 12288 B
#define STAGES 6
#define DLY 2                            // store-read release slack (< STAGES)
#define NT 320                           // 8 fixup warps + loader warp + storer warp
#define GRID 304                         // 2 CTAs/SM * 152 SMs

// smem float offsets
#define SM_M   (STAGES * TILE_F)                 // 18432
#define SM_C   (SM_M + 4 * 16 * 16)              // +1024
#define SM_BARF (SM_C + 64)                      // even float idx -> 8B aligned
#define SM_BYTES (SM_BARF * 4 + 3 * STAGES * 8)

__device__ __forceinline__ void mbar_init(uint32_t a, uint32_t cnt) {
    asm volatile("mbarrier.init.shared.b64 [%0], %1;" :: "r"(a), "r"(cnt) : "memory");
}
__device__ __forceinline__ void mbar_arrive(uint32_t a) {
    asm volatile("mbarrier.arrive.shared.b64 _, [%0];" :: "r"(a) : "memory");
}
__device__ __forceinline__ void mbar_expect_tx(uint32_t a, uint32_t bytes) {
    asm volatile("mbarrier.arrive.expect_tx.shared.b64 _, [%0], %1;" :: "r"(a), "r"(bytes) : "memory");
}
__device__ __forceinline__ void mbar_wait(uint32_t a, uint32_t parity) {
    asm volatile(
        "{\n\t.reg .pred P;\n\t"
        "LW_%=:\n\t"
        "mbarrier.try_wait.parity.acquire.cta.shared::cta.b64 P, [%0], %1, 0x989680;\n\t"
        "@P bra LD_%=;\n\t"
        "bra LW_%=;\n\t"
        "LD_%=:\n\t}"
        :: "r"(a), "r"(parity) : "memory");
}
__device__ __forceinline__ void bulk_ld(uint32_t dst, const void* src, uint32_t bytes, uint32_t bar) {
    asm volatile("cp.async.bulk.shared::cta.global.mbarrier::complete_tx::bytes [%0], [%1], %2, [%3];"
                 :: "r"(dst), "l"(src), "r"(bytes), "r"(bar) : "memory");
}
__device__ __forceinline__ void bulk_st(void* dst, uint32_t src, uint32_t bytes) {
    asm volatile("cp.async.bulk.global.shared::cta.bulk_group [%0], [%1], %2;"
                 :: "l"(dst), "r"(src), "r"(bytes) : "memory");
}
__device__ __forceinline__ void bulk_commit() {
    asm volatile("cp.async.bulk.commit_group;" ::: "memory");
}
template<int N>
__device__ __forceinline__ void bulk_wait_read() {
    asm volatile("cp.async.bulk.wait_group.read %0;" :: "n"(N) : "memory");
}
__device__ __forceinline__ void fence_async() {
    asm volatile("fence.proxy.async.shared::cta;" ::: "memory");
}
__device__ __forceinline__ int start_of(int g) {
    return g == 0 ? 0 : g == 1 ? 752 : g == 2 ? 184 : 568;
}

__global__ __launch_bounds__(NT) void minireft_ws(
    const float* __restrict__ base, float* __restrict__ out,
    const float* __restrict__ Wp, const float* __restrict__ bp,
    const float* __restrict__ Ws, const float* __restrict__ bs,
    int B, int nTiles)
{
    extern __shared__ float smem[];
    float* sM = smem + SM_M;   // [4][16][16]: sM[(g*16+e)*16+l]
    float* sC = smem + SM_C;   // [4][16]
    const uint32_t smem_u32 = (uint32_t)__cvta_generic_to_shared(smem);
    const uint32_t FULLB  = smem_u32 + SM_BARF * 4;
    const uint32_t PATCHB = FULLB + STAGES * 8;
    const uint32_t EMPTYB = PATCHB + STAGES * 8;

    const int tid = threadIdx.x;

    // ---- fold weights ----
    for (int idx = tid; idx < 4 * 16 * 16; idx += NT) {
        int g = idx >> 8, e = (idx >> 4) & 15, l = idx & 15;
        float acc = 0.f;
        #pragma unroll
        for (int r = 0; r < 8; r++) {
            float wp = Wp[g * 128 + r * 16 + e];
            float ws = Ws[g * 128 + r * 16 + e];
            acc += (ws - wp) * Wp[g * 128 + r * 16 + l];
        }
        sM[idx] = acc;
    }
    for (int idx = tid; idx < 4 * 16; idx += NT) {
        int g = idx >> 4, l = idx & 15;
        float acc = 0.f;
        #pragma unroll
        for (int r = 0; r < 8; r++)
            acc += (bs[g * 8 + r] - bp[g * 8 + r]) * Wp[g * 128 + r * 16 + l];
        sC[idx] = acc;
    }
    if (tid < STAGES)                mbar_init(FULLB  + tid * 8, 1);
    else if (tid < 2 * STAGES)       mbar_init(PATCHB + (tid - STAGES) * 8, 256);
    else if (tid < 3 * STAGES)       mbar_init(EMPTYB + (tid - 2 * STAGES) * 8, 1);
    __syncthreads();
    if (tid == 0) fence_async();
    __syncthreads();

    // ---- remainder rows (B % T_ROWS) on block 0, plain path ----
    if (blockIdx.x == 0 && (B & (T_ROWS - 1))) {
        const long long remStart = (long long)nTiles * T_ROWS;
        for (long long row = remStart; row < B; row++) {
            for (int c = tid; c < 768; c += NT)
                out[row * 768 + c] = base[row * 768 + c];
            __syncthreads();
            if (tid < 64) {
                int g = tid >> 4, l = tid & 15;
                int st = start_of(g);
                float d = sC[g * 16 + l];
                #pragma unroll
                for (int e = 0; e < 16; e++)
                    d += sM[(g * 16 + e) * 16 + l] * base[row * 768 + st + e];
                out[row * 768 + st + l] = base[row * 768 + st + l] + d;
            }
            __syncthreads();
        }
    }

    const int bid = blockIdx.x;
    const int count = (bid < nTiles) ? (nTiles - bid + GRID - 1) / GRID : 0;
    const int wid = tid >> 5;

    if (wid < 8) {
        // ---------------- fixup: 1 edited float per thread per tile -------
        const int row = tid >> 6;          // 0..3
        const int g   = (tid >> 4) & 3;
        const int l   = tid & 15;
        const int xoff = row * 768 + start_of(g);
        const float cl = sC[g * 16 + l];

        int s = 0, p = 0;
        for (int k = 0; k < count; k++) {
            mbar_wait(FULLB + s * 8, p);
            float* sb = smem + s * TILE_F;
            float x[16];
            #pragma unroll
            for (int e = 0; e < 16; e++) x[e] = sb[xoff + e];
            float d = cl;
            #pragma unroll
            for (int e = 0; e < 16; e++)
                d += sM[(g * 16 + e) * 16 + l] * x[e];
            __syncwarp();
            sb[xoff + l] = x[l] + d;
            fence_async();
            mbar_arrive(PATCHB + s * 8);
            if (++s == STAGES) { s = 0; p ^= 1; }
        }
    } else if (wid == 8) {
        // ---------------- loader ----------------
        if ((tid & 31) == 0) {
            int s = 0, pe = 1;                   // first empty-wait passes
            long long tile = bid;
            for (int k = 0; k < count; k++, tile += GRID) {
                mbar_wait(EMPTYB + s * 8, pe);
                mbar_expect_tx(FULLB + s * 8, TILE_BYTES);
                bulk_ld(smem_u32 + (uint32_t)(s * TILE_BYTES),
                        base + tile * TILE_F, TILE_BYTES, FULLB + s * 8);
                if (++s == STAGES) { s = 0; pe ^= 1; }
            }
        }
    } else {
        // ---------------- storer ----------------
        if ((tid & 31) == 0) {
            int s = 0, p = 0;
            long long tile = bid;
            for (int k = 0; k < count; k++, tile += GRID) {
                mbar_wait(PATCHB + s * 8, p);
                bulk_st(out + tile * TILE_F,
                        smem_u32 + (uint32_t)(s * TILE_BYTES), TILE_BYTES);
                bulk_commit();
                const int j = k - DLY;
                if (j >= 0) {
                    bulk_wait_read<DLY>();       // group j's smem read done
                    int sj = s - DLY; if (sj < 0) sj += STAGES;
                    mbar_arrive(EMPTYB + sj * 8);
                }
                if (++s == STAGES) { s = 0; p ^= 1; }
            }
        }
    }
}

extern "C" void kernel_launch(void* const* d_in, const int* in_sizes, int n_in,
                              void* d_out, int out_size)
{
    const float* base = (const float*)d_in[0];  // [1, B, 768]
    const float* Wp   = (const float*)d_in[1];
    const float* bp   = (const float*)d_in[2];
    const float* Ws   = (const float*)d_in[3];
    const float* bs   = (const float*)d_in[4];
    float* out = (float*)d_out;

    const int B = in_sizes[0] / 768;
    const int nTiles = B / T_ROWS;

    static int configured = 0;
    if (!configured) {
        cudaFuncSetAttribute(minireft_ws,
                             cudaFuncAttributeMaxDynamicSharedMemorySize, SM_BYTES);
        configured = 1;
    }

    minireft_ws<<<GRID, NT, SM_BYTES>>>(base, out, Wp, bp, Ws, bs, B, nTiles);
}

// round 9
// speedup vs baseline: 1.3868x; 1.3868x over previous
#include <cuda_runtime.h>
#include <cstdint>

// NoReFT on [B,768] fp32, regions start {0,752,184,568}, width 16.
// TMA G->S load pipeline (3 stages x 12KB = 4 rows), register consume with
// region fixup (vectorized gather), STG.128 .cs stores. 6 CTAs/SM.

#define T_ROWS 4
#define TILE_F (T_ROWS * 768)            // 3072 floats
#define TILE_F4 (TILE_F / 4)             // 768
#define TILE_BYTES (TILE_F * 4)          // 12288 B
#define STAGES 3
#define NT 256
#define MAXGRID 2048

// smem float offsets
#define SM_M   (STAGES * TILE_F)                 // 9216
#define SM_C   (SM_M + 4 * 16 * 16)
#define SM_BAR (SM_C + 64)                       // even float idx -> 8B aligned
#define SM_BYTES (SM_BAR * 4 + STAGES * 8)

__device__ __forceinline__ void mbar_init(uint32_t a, uint32_t cnt) {
    asm volatile("mbarrier.init.shared.b64 [%0], %1;" :: "r"(a), "r"(cnt) : "memory");
}
__device__ __forceinline__ void mbar_expect_tx(uint32_t a, uint32_t bytes) {
    asm volatile("mbarrier.arrive.expect_tx.shared.b64 _, [%0], %1;" :: "r"(a), "r"(bytes) : "memory");
}
__device__ __forceinline__ void mbar_wait(uint32_t a, uint32_t parity) {
    asm volatile(
        "{\n\t.reg .pred P;\n\t"
        "LW_%=:\n\t"
        "mbarrier.try_wait.parity.acquire.cta.shared::cta.b64 P, [%0], %1, 0x989680;\n\t"
        "@P bra LD_%=;\n\t"
        "bra LW_%=;\n\t"
        "LD_%=:\n\t}"
        :: "r"(a), "r"(parity) : "memory");
}
__device__ __forceinline__ void bulk_ld(uint32_t dst, const void* src, uint32_t bytes, uint32_t bar) {
    asm volatile("cp.async.bulk.shared::cta.global.mbarrier::complete_tx::bytes [%0], [%1], %2, [%3];"
                 :: "r"(dst), "l"(src), "r"(bytes), "r"(bar) : "memory");
}

__device__ __forceinline__ int region_of(int c4, int& off) {
    if (c4 < 4)                 { off = c4;       return 0; }
    if (c4 >= 188)              { off = c4 - 188; return 1; }
    if (c4 >= 46 && c4 < 50)    { off = c4 - 46;  return 2; }
    if (c4 >= 142 && c4 < 146)  { off = c4 - 142; return 3; }
    off = 0; return -1;
}
__device__ __forceinline__ int start_of(int g) {
    return g == 0 ? 0 : g == 1 ? 752 : g == 2 ? 184 : 568;
}

__global__ __launch_bounds__(NT, 6) void minireft_v9(
    const float* __restrict__ base, float* __restrict__ out,
    const float* __restrict__ Wp, const float* __restrict__ bp,
    const float* __restrict__ Ws, const float* __restrict__ bs,
    int B, int nTiles, int grid)
{
    extern __shared__ float smem[];
    float* sM = smem + SM_M;   // [4][16][16]: sM[(g*16+e)*16+l]
    float* sC = smem + SM_C;   // [4][16]
    const uint32_t smem_u32 = (uint32_t)__cvta_generic_to_shared(smem);
    const uint32_t bar0 = smem_u32 + SM_BAR * 4;

    const int tid = threadIdx.x;

    // ---- fold weights ----
    for (int idx = tid; idx < 4 * 16 * 16; idx += NT) {
        int g = idx >> 8, e = (idx >> 4) & 15, l = idx & 15;
        float acc = 0.f;
        #pragma unroll
        for (int r = 0; r < 8; r++) {
            float wp = Wp[g * 128 + r * 16 + e];
            float ws = Ws[g * 128 + r * 16 + e];
            acc += (ws - wp) * Wp[g * 128 + r * 16 + l];
        }
        sM[idx] = acc;
    }
    for (int idx = tid; idx < 4 * 16; idx += NT) {
        int g = idx >> 4, l = idx & 15;
        float acc = 0.f;
        #pragma unroll
        for (int r = 0; r < 8; r++)
            acc += (bs[g * 8 + r] - bp[g * 8 + r]) * Wp[g * 128 + r * 16 + l];
        sC[idx] = acc;
    }
    if (tid < STAGES) mbar_init(bar0 + tid * 8, 1);
    __syncthreads();

    // ---- remainder rows (B % T_ROWS) on block 0 (plain path) ----
    if (blockIdx.x == 0 && (B & (T_ROWS - 1))) {
        const long long remStart = (long long)nTiles * T_ROWS;
        for (long long row = remStart; row < B; row++) {
            for (int c = tid; c < 768; c += NT)
                out[row * 768 + c] = base[row * 768 + c];
            __syncthreads();
            if (tid < 64) {
                int g = tid >> 4, l = tid & 15;
                int st = start_of(g);
                float d = sC[g * 16 + l];
                #pragma unroll
                for (int e = 0; e < 16; e++)
                    d += sM[(g * 16 + e) * 16 + l] * base[row * 768 + st + e];
                out[row * 768 + st + l] = base[row * 768 + st + l] + d;
            }
            __syncthreads();
        }
    }

    // ---- per-thread geometry: 3 chunks per thread ----
    int rowb_[3], g_[3], q_[3];
    #pragma unroll
    for (int j = 0; j < 3; j++) {
        int chunk = tid + NT * j;          // 0..767
        int row = chunk / 192;
        int c4 = chunk - row * 192;
        rowb_[j] = row * 768;
        int off; g_[j] = region_of(c4, off); q_[j] = off * 4;
    }

    const int bid = blockIdx.x;
    int count = 0;
    if (bid < nTiles) count = (nTiles - bid + grid - 1) / grid;

    // prologue: fill pipeline
    if (tid == 0) {
        int pre = count < STAGES ? count : STAGES;
        for (int k = 0; k < pre; k++) {
            long long tile = (long long)bid + (long long)k * grid;
            mbar_expect_tx(bar0 + k * 8, TILE_BYTES);
            bulk_ld(smem_u32 + (uint32_t)(k * TILE_BYTES),
                    base + tile * TILE_F, TILE_BYTES, bar0 + k * 8);
        }
    }

    int s = 0, p = 0;
    for (int k = 0; k < count; k++) {
        mbar_wait(bar0 + s * 8, p);

        const float* sb = smem + s * TILE_F;
        const float4* sb4 = (const float4*)sb;
        const long long tile = (long long)bid + (long long)k * grid;
        float4* op = (float4*)out + tile * TILE_F4;

        #pragma unroll
        for (int j = 0; j < 3; j++) {
            const int chunk = tid + NT * j;
            float4 v = sb4[chunk];
            const int g = g_[j];
            if (g >= 0) {
                const float4* x4 = (const float4*)(sb + rowb_[j] + start_of(g));
                const float4 X0 = x4[0], X1 = x4[1], X2 = x4[2], X3 = x4[3];
                const float x[16] = { X0.x, X0.y, X0.z, X0.w,
                                      X1.x, X1.y, X1.z, X1.w,
                                      X2.x, X2.y, X2.z, X2.w,
                                      X3.x, X3.y, X3.z, X3.w };
                const int q = q_[j];
                float d0 = sC[g*16+q], d1 = sC[g*16+q+1],
                      d2 = sC[g*16+q+2], d3 = sC[g*16+q+3];
                #pragma unroll
                for (int e = 0; e < 16; e++) {
                    const float xe = x[e];
                    d0 += sM[(g*16+e)*16+q  ] * xe;
                    d1 += sM[(g*16+e)*16+q+1] * xe;
                    d2 += sM[(g*16+e)*16+q+2] * xe;
                    d3 += sM[(g*16+e)*16+q+3] * xe;
                }
                v.x += d0; v.y += d1; v.z += d2; v.w += d3;
            }
            __stcs(op + chunk, v);
        }

        __syncthreads();   // everyone done reading stage s

        if (tid == 0 && k + STAGES < count) {
            long long nt = (long long)bid + (long long)(k + STAGES) * grid;
            mbar_expect_tx(bar0 + s * 8, TILE_BYTES);
            bulk_ld(smem_u32 + (uint32_t)(s * TILE_BYTES),
                    base + nt * TILE_F, TILE_BYTES, bar0 + s * 8);
        }

        if (++s == STAGES) { s = 0; p ^= 1; }
    }
}

extern "C" void kernel_launch(void* const* d_in, const int* in_sizes, int n_in,
                              void* d_out, int out_size)
{
    const float* base = (const float*)d_in[0];  // [1, B, 768]
    const float* Wp   = (const float*)d_in[1];
    const float* bp   = (const float*)d_in[2];
    const float* Ws   = (const float*)d_in[3];
    const float* bs   = (const float*)d_in[4];
    float* out = (float*)d_out;

    const int B = in_sizes[0] / 768;
    const int nTiles = B / T_ROWS;

    int grid = nTiles < MAXGRID ? (nTiles > 0 ? nTiles : 1) : MAXGRID;

    static int configured = 0;
    if (!configured) {
        cudaFuncSetAttribute(minireft_v9,
                             cudaFuncAttributeMaxDynamicSharedMemorySize, SM_BYTES);
        configured = 1;
    }

    minireft_v9<<<grid, NT, SM_BYTES>>>(base, out, Wp, bp, Ws, bs, B, nTiles, grid);
}

// round 10
// speedup vs baseline: 1.4570x; 1.0507x over previous
#include <cuda_runtime.h>
#include <cstdint>

// NoReFT on [B,768] fp32, regions start {0,752,184,568}, width 16.
// TMA G->S pipeline (3 stages x 12KB = 4 rows). Per tile: in-smem patch of the
// 256 edited floats (M columns in registers), then uniform branch-free
// LDS.128->STG.128 copy. 6 CTAs/SM.

#define T_ROWS 4
#define TILE_F (T_ROWS * 768)            // 3072 floats
#define TILE_F4 (TILE_F / 4)             // 768
#define TILE_BYTES (TILE_F * 4)          // 12288 B
#define STAGES 3
#define NT 256
#define MAXGRID 2048

// steady-state smem: ring + barriers only
#define SM_BAR (STAGES * TILE_F)                 // even float idx -> 8B aligned
#define SM_BYTES (SM_BAR * 4 + STAGES * 8)

__device__ __forceinline__ void mbar_init(uint32_t a, uint32_t cnt) {
    asm volatile("mbarrier.init.shared.b64 [%0], %1;" :: "r"(a), "r"(cnt) : "memory");
}
__device__ __forceinline__ void mbar_expect_tx(uint32_t a, uint32_t bytes) {
    asm volatile("mbarrier.arrive.expect_tx.shared.b64 _, [%0], %1;" :: "r"(a), "r"(bytes) : "memory");
}
__device__ __forceinline__ void mbar_wait(uint32_t a, uint32_t parity) {
    asm volatile(
        "{\n\t.reg .pred P;\n\t"
        "LW_%=:\n\t"
        "mbarrier.try_wait.parity.acquire.cta.shared::cta.b64 P, [%0], %1, 0x989680;\n\t"
        "@P bra LD_%=;\n\t"
        "bra LW_%=;\n\t"
        "LD_%=:\n\t}"
        :: "r"(a), "r"(parity) : "memory");
}
__device__ __forceinline__ void bulk_ld(uint32_t dst, const void* src, uint32_t bytes, uint32_t bar) {
    asm volatile("cp.async.bulk.shared::cta.global.mbarrier::complete_tx::bytes [%0], [%1], %2, [%3];"
                 :: "r"(dst), "l"(src), "r"(bytes), "r"(bar) : "memory");
}
__device__ __forceinline__ int start_of(int g) {
    return g == 0 ? 0 : g == 1 ? 752 : g == 2 ? 184 : 568;
}

__global__ __launch_bounds__(NT, 6) void minireft_v10(
    const float* __restrict__ base, float* __restrict__ out,
    const float* __restrict__ Wp, const float* __restrict__ bp,
    const float* __restrict__ Ws, const float* __restrict__ bs,
    int B, int nTiles, int grid)
{
    extern __shared__ float smem[];
    const uint32_t smem_u32 = (uint32_t)__cvta_generic_to_shared(smem);
    const uint32_t bar0 = smem_u32 + SM_BAR * 4;

    const int tid = threadIdx.x;

    // ---- thread's edited-float identity: one per (row, g, l) ----
    const int prow = tid >> 6;          // 0..3 tile row
    const int g    = (tid >> 4) & 3;    // region
    const int l    = tid & 15;          // channel within region
    const int xoff = prow * 768 + start_of(g);

    // ---- fold weights into scratch smem (ring area, pre-pipeline), then
    //      load this thread's M column + bias into registers ----
    {
        float* sM = smem;               // [4][16][16]: sM[(g*16+e)*16+l]
        float* sC = smem + 1024;        // [4][16]
        for (int idx = tid; idx < 4 * 16 * 16; idx += NT) {
            int gg = idx >> 8, e = (idx >> 4) & 15, ll = idx & 15;
            float acc = 0.f;
            #pragma unroll
            for (int r = 0; r < 8; r++) {
                float wp = Wp[gg * 128 + r * 16 + e];
                float ws = Ws[gg * 128 + r * 16 + e];
                acc += (ws - wp) * Wp[gg * 128 + r * 16 + ll];
            }
            sM[idx] = acc;
        }
        for (int idx = tid; idx < 4 * 16; idx += NT) {
            int gg = idx >> 4, ll = idx & 15;
            float acc = 0.f;
            #pragma unroll
            for (int r = 0; r < 8; r++)
                acc += (bs[gg * 8 + r] - bp[gg * 8 + r]) * Wp[gg * 128 + r * 16 + ll];
            sC[idx] = acc;
        }
        __syncthreads();

        // registers: Mv[e] = sM[g][e][l], cl = sC[g][l]
        float Mv[16], cl;
        #pragma unroll
        for (int e = 0; e < 16; e++) Mv[e] = sM[(g * 16 + e) * 16 + l];
        cl = sC[g * 16 + l];
        __syncthreads();

        // ---- remainder rows (B % T_ROWS) on block 0, plain path ----
        if (blockIdx.x == 0 && (B & (T_ROWS - 1))) {
            const long long remStart = (long long)nTiles * T_ROWS;
            for (long long row = remStart; row < B; row++) {
                for (int c = tid; c < 768; c += NT)
                    out[row * 768 + c] = base[row * 768 + c];
                __syncthreads();
                if (tid < 64) {   // one thread per (g,l)
                    const int st = start_of(g);
                    float d = cl;
                    #pragma unroll
                    for (int e = 0; e < 16; e++)
                        d += Mv[e] * base[row * 768 + st + e];
                    out[row * 768 + st + l] = base[row * 768 + st + l] + d;
                }
                __syncthreads();
            }
        }

        if (tid < STAGES) mbar_init(bar0 + tid * 8, 1);
        __syncthreads();

        const int bid = blockIdx.x;
        int count = 0;
        if (bid < nTiles) count = (nTiles - bid + grid - 1) / grid;

        // prologue: fill pipeline
        if (tid == 0) {
            int pre = count < STAGES ? count : STAGES;
            for (int k = 0; k < pre; k++) {
                long long tile = (long long)bid + (long long)k * grid;
                mbar_expect_tx(bar0 + k * 8, TILE_BYTES);
                bulk_ld(smem_u32 + (uint32_t)(k * TILE_BYTES),
                        base + tile * TILE_F, TILE_BYTES, bar0 + k * 8);
            }
        }

        int s = 0, p = 0;
        for (int k = 0; k < count; k++) {
            mbar_wait(bar0 + s * 8, p);

            float* sb = smem + s * TILE_F;

            // ---- phase 1: in-place patch of this thread's edited float ----
            {
                const float4* x4 = (const float4*)(sb + xoff);
                const float4 X0 = x4[0], X1 = x4[1], X2 = x4[2], X3 = x4[3];
                float d = cl;
                d += Mv[0] * X0.x;  d += Mv[1] * X0.y;
                d += Mv[2] * X0.z;  d += Mv[3] * X0.w;
                d += Mv[4] * X1.x;  d += Mv[5] * X1.y;
                d += Mv[6] * X1.z;  d += Mv[7] * X1.w;
                d += Mv[8] * X2.x;  d += Mv[9] * X2.y;
                d += Mv[10] * X2.z; d += Mv[11] * X2.w;
                d += Mv[12] * X3.x; d += Mv[13] * X3.y;
                d += Mv[14] * X3.z; d += Mv[15] * X3.w;
                const float xl = sb[xoff + l];
                __syncwarp();                 // all reads of x before any write
                sb[xoff + l] = xl + d;
            }
            __syncthreads();                  // patch visible to all copy warps

            // ---- phase 2: uniform branch-free copy ----
            {
                const float4* sb4 = (const float4*)sb;
                const long long tile = (long long)bid + (long long)k * grid;
                float4* op = (float4*)out + tile * TILE_F4;
                float4 v0 = sb4[tid];
                float4 v1 = sb4[tid + NT];
                float4 v2 = sb4[tid + 2 * NT];
                __stcs(op + tid, v0);
                __stcs(op + tid + NT, v1);
                __stcs(op + tid + 2 * NT, v2);
            }

            __syncthreads();   // everyone done reading stage s

            if (tid == 0 && k + STAGES < count) {
                long long nt = (long long)bid + (long long)(k + STAGES) * grid;
                mbar_expect_tx(bar0 + s * 8, TILE_BYTES);
                bulk_ld(smem_u32 + (uint32_t)(s * TILE_BYTES),
                        base + nt * TILE_F, TILE_BYTES, bar0 + s * 8);
            }

            if (++s == STAGES) { s = 0; p ^= 1; }
        }
    }
}

extern "C" void kernel_launch(void* const* d_in, const int* in_sizes, int n_in,
                              void* d_out, int out_size)
{
    const float* base = (const float*)d_in[0];  // [1, B, 768]
    const float* Wp   = (const float*)d_in[1];
    const float* bp   = (const float*)d_in[2];
    const float* Ws   = (const float*)d_in[3];
    const float* bs   = (const float*)d_in[4];
    float* out = (float*)d_out;

    const int B = in_sizes[0] / 768;
    const int nTiles = B / T_ROWS;

    int grid = nTiles < MAXGRID ? (nTiles > 0 ? nTiles : 1) : MAXGRID;

    static int configured = 0;
    if (!configured) {
        cudaFuncSetAttribute(minireft_v10,
                             cudaFuncAttributeMaxDynamicSharedMemorySize, SM_BYTES);
        configured = 1;
    }

    minireft_v10<<<grid, NT, SM_BYTES>>>(base, out, Wp, bp, Ws, bs, B, nTiles, grid);
}